// round 5
// baseline (speedup 1.0000x reference)
#include <cuda_runtime.h>
#include <math.h>

// Problem constants
#define BDIM 8
#define TDIM 2048
#define HDIM 1024
#define MDIM (BDIM * TDIM)        // 16384 rows
#define MH   (MDIM * HDIM)        // 16,777,216 elements

// Scratch (allocation-free rule: __device__ globals)
__device__ float g_xk[MH];
__device__ float g_xv[MH];
__device__ float g_xr[MH];
__device__ float g_k[MH];
__device__ float g_v[MH];
__device__ float g_r[MH];
__device__ float g_a[MH];   // r * wkv

// ---------------------------------------------------------------------------
// Kernel 1: token-shift mix.  xk = x*mk + x_prev*(1-mk)  (same for v, r)
// ---------------------------------------------------------------------------
__global__ void mix_kernel(const float4* __restrict__ x,
                           const float4* __restrict__ mk4,
                           const float4* __restrict__ mv4,
                           const float4* __restrict__ mr4,
                           float4* __restrict__ xk,
                           float4* __restrict__ xv,
                           float4* __restrict__ xr)
{
    const int H4 = HDIM / 4;
    int i = blockIdx.x * blockDim.x + threadIdx.x;   // grid sized exactly
    int h4 = i % H4;
    int m  = i / H4;
    int t  = m & (TDIM - 1);

    float4 xc = x[i];
    float4 xp = make_float4(0.f, 0.f, 0.f, 0.f);
    if (t != 0) xp = x[i - H4];

    float4 mk = mk4[h4];
    float4 mv = mv4[h4];
    float4 mr = mr4[h4];

    float4 ok, ov, orr;
    ok.x = xc.x * mk.x + xp.x * (1.f - mk.x);
    ok.y = xc.y * mk.y + xp.y * (1.f - mk.y);
    ok.z = xc.z * mk.z + xp.z * (1.f - mk.z);
    ok.w = xc.w * mk.w + xp.w * (1.f - mk.w);
    ov.x = xc.x * mv.x + xp.x * (1.f - mv.x);
    ov.y = xc.y * mv.y + xp.y * (1.f - mv.y);
    ov.z = xc.z * mv.z + xp.z * (1.f - mv.z);
    ov.w = xc.w * mv.w + xp.w * (1.f - mv.w);
    orr.x = xc.x * mr.x + xp.x * (1.f - mr.x);
    orr.y = xc.y * mr.y + xp.y * (1.f - mr.y);
    orr.z = xc.z * mr.z + xp.z * (1.f - mr.z);
    orr.w = xc.w * mr.w + xp.w * (1.f - mr.w);

    xk[i] = ok;
    xv[i] = ov;
    xr[i] = orr;
}

// ---------------------------------------------------------------------------
// SGEMM core:  C[m,o] = sum_h A[m,h] * W[o,h]   (A, W both K-contiguous)
// 128x128 tile, BK=8, 256 threads, 8x8 microtile, 2-stage smem double buffer.
// One __syncthreads per K-step; global prefetch overlaps compute.
// ---------------------------------------------------------------------------
__device__ __forceinline__ void gemm_body(const float* __restrict__ A,
                                          const float* __restrict__ W,
                                          float* __restrict__ C,
                                          int act)
{
    const int K = HDIM;
    __shared__ float As[2][8][132];   // +4 pad: conflict-free stores
    __shared__ float Bs[2][8][132];

    int tid   = threadIdx.x;
    int mBase = blockIdx.y * 128;
    int nBase = blockIdx.x * 128;

    int lrow = tid >> 1;          // 0..127
    int lcol = (tid & 1) * 4;     // 0 or 4

    const float* Aload = A + (size_t)(mBase + lrow) * K + lcol;
    const float* Wload = W + (size_t)(nBase + lrow) * K + lcol;

    int ty = tid >> 4;            // 0..15 -> m microtile
    int tx = tid & 15;            // 0..15 -> n microtile

    float acc[8][8];
#pragma unroll
    for (int i = 0; i < 8; i++)
#pragma unroll
        for (int j = 0; j < 8; j++) acc[i][j] = 0.f;

    // Preload tile 0 into buffer 0
    {
        float4 a = *(const float4*)(Aload);
        float4 b = *(const float4*)(Wload);
        As[0][lcol + 0][lrow] = a.x;
        As[0][lcol + 1][lrow] = a.y;
        As[0][lcol + 2][lrow] = a.z;
        As[0][lcol + 3][lrow] = a.w;
        Bs[0][lcol + 0][lrow] = b.x;
        Bs[0][lcol + 1][lrow] = b.y;
        Bs[0][lcol + 2][lrow] = b.z;
        Bs[0][lcol + 3][lrow] = b.w;
    }
    __syncthreads();

    int buf = 0;
    for (int k0 = 0; k0 < K; k0 += 8) {
        // Prefetch next K-tile into registers (overlaps compute below)
        float4 a2, b2;
        bool more = (k0 + 8 < K);
        if (more) {
            a2 = *(const float4*)(Aload + k0 + 8);
            b2 = *(const float4*)(Wload + k0 + 8);
        }

        // Compute on current buffer
#pragma unroll
        for (int kk = 0; kk < 8; kk++) {
            float4 a0 = *(const float4*)&As[buf][kk][ty * 8];
            float4 a1 = *(const float4*)&As[buf][kk][ty * 8 + 4];
            float4 b0 = *(const float4*)&Bs[buf][kk][tx * 8];
            float4 b1 = *(const float4*)&Bs[buf][kk][tx * 8 + 4];
            float ar[8] = {a0.x, a0.y, a0.z, a0.w, a1.x, a1.y, a1.z, a1.w};
            float br[8] = {b0.x, b0.y, b0.z, b0.w, b1.x, b1.y, b1.z, b1.w};
#pragma unroll
            for (int i = 0; i < 8; i++)
#pragma unroll
                for (int j = 0; j < 8; j++)
                    acc[i][j] += ar[i] * br[j];
        }

        if (more) {
            int nb = buf ^ 1;
            As[nb][lcol + 0][lrow] = a2.x;
            As[nb][lcol + 1][lrow] = a2.y;
            As[nb][lcol + 2][lrow] = a2.z;
            As[nb][lcol + 3][lrow] = a2.w;
            Bs[nb][lcol + 0][lrow] = b2.x;
            Bs[nb][lcol + 1][lrow] = b2.y;
            Bs[nb][lcol + 2][lrow] = b2.z;
            Bs[nb][lcol + 3][lrow] = b2.w;
            __syncthreads();
            buf = nb;
        }
    }

#pragma unroll
    for (int i = 0; i < 8; i++) {
        int row = mBase + ty * 8 + i;
        float* Crow = C + (size_t)row * HDIM + nBase + tx * 8;
        float vals[8];
#pragma unroll
        for (int j = 0; j < 8; j++) {
            float v = acc[i][j];
            if (act) v = 1.f / (1.f + __expf(-v));
            vals[j] = v;
        }
        *(float4*)(Crow)     = make_float4(vals[0], vals[1], vals[2], vals[3]);
        *(float4*)(Crow + 4) = make_float4(vals[4], vals[5], vals[6], vals[7]);
    }
}

// Single-GEMM wrapper (output projection)
__global__ __launch_bounds__(256) void gemm_kernel(const float* __restrict__ A,
                                                   const float* __restrict__ W,
                                                   float* __restrict__ C,
                                                   int act)
{
    gemm_body(A, W, C, act);
}

// Batched 3-GEMM wrapper: z selects (A,W,C); z==2 gets sigmoid epilogue.
__global__ __launch_bounds__(256) void gemm3_kernel(const float* __restrict__ A0,
                                                    const float* __restrict__ W0,
                                                    float* __restrict__ C0,
                                                    const float* __restrict__ A1,
                                                    const float* __restrict__ W1,
                                                    float* __restrict__ C1,
                                                    const float* __restrict__ A2,
                                                    const float* __restrict__ W2,
                                                    float* __restrict__ C2)
{
    int z = blockIdx.z;
    const float* A = (z == 0) ? A0 : (z == 1) ? A1 : A2;
    const float* W = (z == 0) ? W0 : (z == 1) ? W1 : W2;
    float*       C = (z == 0) ? C0 : (z == 1) ? C1 : C2;
    gemm_body(A, W, C, z == 2 ? 1 : 0);
}

// ---------------------------------------------------------------------------
// WKV scan.  One thread per (b, h) channel, sequential over T.
// Fuses a = r * wkv.
// ---------------------------------------------------------------------------
__global__ void wkv_kernel(const float* __restrict__ k,
                           const float* __restrict__ v,
                           const float* __restrict__ r,
                           const float* __restrict__ w_,
                           const float* __restrict__ u_,
                           float* __restrict__ outA)
{
    int c = blockIdx.x * blockDim.x + threadIdx.x;   // 0..8191
    int b = c >> 10;
    int h = c & (HDIM - 1);
    float w = w_[h];
    float u = u_[h];

    int idx = b * TDIM * HDIM + h;

    float aa = 0.f, bb = 0.f, pp = -1e38f;
#pragma unroll 4
    for (int t = 0; t < TDIM; t++) {
        float kt = k[idx];
        float vt = v[idx];
        float rt = r[idx];

        float ww = u + kt;
        float p  = fmaxf(pp, ww);
        float e1 = __expf(pp - p);
        float e2 = __expf(ww - p);
        float num = e1 * aa + e2 * vt;
        float den = e1 * bb + e2 + 1e-9f;
        float wkv = __fdividef(num, den);
        outA[idx] = rt * wkv;

        float ww2 = w + pp;
        float p2  = fmaxf(ww2, kt);
        float e1b = __expf(ww2 - p2);
        float e2b = __expf(kt - p2);
        aa = e1b * aa + e2b * vt;
        bb = e1b * bb + e2b;
        pp = p2;

        idx += HDIM;
    }
}

// ---------------------------------------------------------------------------
// Launch.  Input order (metadata): x, time_decay, time_first, time_mix_k,
// time_mix_v, time_mix_r, W_k, W_v, W_r, W_o.  Output: float32 [B,T,H].
// ---------------------------------------------------------------------------
extern "C" void kernel_launch(void* const* d_in, const int* in_sizes, int n_in,
                              void* d_out, int out_size)
{
    const float* x   = (const float*)d_in[0];
    const float* td  = (const float*)d_in[1];
    const float* tf  = (const float*)d_in[2];
    const float* tmk = (const float*)d_in[3];
    const float* tmv = (const float*)d_in[4];
    const float* tmr = (const float*)d_in[5];
    const float* Wk  = (const float*)d_in[6];
    const float* Wv  = (const float*)d_in[7];
    const float* Wr  = (const float*)d_in[8];
    const float* Wo  = (const float*)d_in[9];
    float* out = (float*)d_out;

    void *pxk, *pxv, *pxr, *pk, *pv, *pr, *pa;
    cudaGetSymbolAddress(&pxk, g_xk);
    cudaGetSymbolAddress(&pxv, g_xv);
    cudaGetSymbolAddress(&pxr, g_xr);
    cudaGetSymbolAddress(&pk,  g_k);
    cudaGetSymbolAddress(&pv,  g_v);
    cudaGetSymbolAddress(&pr,  g_r);
    cudaGetSymbolAddress(&pa,  g_a);

    // 1) token-shift mix
    mix_kernel<<<MH / 4 / 256, 256>>>((const float4*)x,
                                      (const float4*)tmk,
                                      (const float4*)tmv,
                                      (const float4*)tmr,
                                      (float4*)pxk, (float4*)pxv, (float4*)pxr);

    // 2) three input GEMMs in one launch (sigmoid fused into r via z==2)
    dim3 g3(HDIM / 128, MDIM / 128, 3);   // (8, 128, 3)
    gemm3_kernel<<<g3, 256>>>((const float*)pxk, Wk, (float*)pk,
                              (const float*)pxv, Wv, (float*)pv,
                              (const float*)pxr, Wr, (float*)pr);

    // 3) WKV scan + fuse r*wkv
    wkv_kernel<<<BDIM * HDIM / 256, 256>>>((const float*)pk, (const float*)pv,
                                           (const float*)pr, td, tf, (float*)pa);

    // 4) output GEMM
    dim3 gg(HDIM / 128, MDIM / 128);
    gemm_kernel<<<gg, 256>>>((const float*)pa, Wo, out, 0);
}

// round 7
// speedup vs baseline: 1.1336x; 1.1336x over previous
#include <cuda_runtime.h>
#include <math.h>

// Problem constants
#define BDIM 8
#define TDIM 2048
#define HDIM 1024
#define MDIM (BDIM * TDIM)        // 16384 rows
#define MH   (MDIM * HDIM)        // 16,777,216 elements

// Scratch (allocation-free rule: __device__ globals)
__device__ float g_xk[MH];
__device__ float g_xv[MH];
__device__ float g_xr[MH];
__device__ float g_k[MH];
__device__ float g_v[MH];
__device__ float g_r[MH];
__device__ float g_a[MH];   // r * wkv

// ---------------------------------------------------------------------------
// Kernel 1: token-shift mix.  xk = x*mk + x_prev*(1-mk)  (same for v, r)
// ---------------------------------------------------------------------------
__global__ void mix_kernel(const float4* __restrict__ x,
                           const float4* __restrict__ mk4,
                           const float4* __restrict__ mv4,
                           const float4* __restrict__ mr4,
                           float4* __restrict__ xk,
                           float4* __restrict__ xv,
                           float4* __restrict__ xr)
{
    const int H4 = HDIM / 4;
    int i = blockIdx.x * blockDim.x + threadIdx.x;   // grid sized exactly
    int h4 = i % H4;
    int m  = i / H4;
    int t  = m & (TDIM - 1);

    float4 xc = x[i];
    float4 xp = make_float4(0.f, 0.f, 0.f, 0.f);
    if (t != 0) xp = x[i - H4];

    float4 mk = mk4[h4];
    float4 mv = mv4[h4];
    float4 mr = mr4[h4];

    float4 ok, ov, orr;
    ok.x = xc.x * mk.x + xp.x * (1.f - mk.x);
    ok.y = xc.y * mk.y + xp.y * (1.f - mk.y);
    ok.z = xc.z * mk.z + xp.z * (1.f - mk.z);
    ok.w = xc.w * mk.w + xp.w * (1.f - mk.w);
    ov.x = xc.x * mv.x + xp.x * (1.f - mv.x);
    ov.y = xc.y * mv.y + xp.y * (1.f - mv.y);
    ov.z = xc.z * mv.z + xp.z * (1.f - mv.z);
    ov.w = xc.w * mv.w + xp.w * (1.f - mv.w);
    orr.x = xc.x * mr.x + xp.x * (1.f - mr.x);
    orr.y = xc.y * mr.y + xp.y * (1.f - mr.y);
    orr.z = xc.z * mr.z + xp.z * (1.f - mr.z);
    orr.w = xc.w * mr.w + xp.w * (1.f - mr.w);

    xk[i] = ok;
    xv[i] = ov;
    xr[i] = orr;
}

// ---------------------------------------------------------------------------
// SGEMM core:  C[m,o] = sum_h A[m,h] * W[o,h]   (A, W both K-contiguous)
// 128x128 tile, BK=8, 256 threads, 8x8 microtile, 2-stage smem double buffer.
// B-fragment mapping: each thread's n-values are {tx*4..tx*4+3} and
// {64+tx*4..64+tx*4+3} -> warp reads 256B contiguous per LDS.128 ->
// conflict-free smem (was 4-way conflicted at tx*8 stride-32B).
// ---------------------------------------------------------------------------
__device__ __forceinline__ void gemm_body(const float* __restrict__ A,
                                          const float* __restrict__ W,
                                          float* __restrict__ C,
                                          int act)
{
    const int K = HDIM;
    __shared__ float As[2][8][132];   // +4 pad: conflict-free stores
    __shared__ float Bs[2][8][132];

    int tid   = threadIdx.x;
    int mBase = blockIdx.y * 128;
    int nBase = blockIdx.x * 128;

    int lrow = tid >> 1;          // 0..127
    int lcol = (tid & 1) * 4;     // 0 or 4

    const float* Aload = A + (size_t)(mBase + lrow) * K + lcol;
    const float* Wload = W + (size_t)(nBase + lrow) * K + lcol;

    int ty = tid >> 4;            // 0..15 -> m microtile (rows ty*8..ty*8+7)
    int tx = tid & 15;            // 0..15 -> n microtile (cols tx*4 & 64+tx*4)

    float acc[8][8];
#pragma unroll
    for (int i = 0; i < 8; i++)
#pragma unroll
        for (int j = 0; j < 8; j++) acc[i][j] = 0.f;

    // Preload tile 0 into buffer 0
    {
        float4 a = *(const float4*)(Aload);
        float4 b = *(const float4*)(Wload);
        As[0][lcol + 0][lrow] = a.x;
        As[0][lcol + 1][lrow] = a.y;
        As[0][lcol + 2][lrow] = a.z;
        As[0][lcol + 3][lrow] = a.w;
        Bs[0][lcol + 0][lrow] = b.x;
        Bs[0][lcol + 1][lrow] = b.y;
        Bs[0][lcol + 2][lrow] = b.z;
        Bs[0][lcol + 3][lrow] = b.w;
    }
    __syncthreads();

    int buf = 0;
    for (int k0 = 0; k0 < K; k0 += 8) {
        // Prefetch next K-tile into registers (overlaps compute below)
        float4 a2, b2;
        bool more = (k0 + 8 < K);
        if (more) {
            a2 = *(const float4*)(Aload + k0 + 8);
            b2 = *(const float4*)(Wload + k0 + 8);
        }

        // Compute on current buffer
#pragma unroll
        for (int kk = 0; kk < 8; kk++) {
            float4 a0 = *(const float4*)&As[buf][kk][ty * 8];
            float4 a1 = *(const float4*)&As[buf][kk][ty * 8 + 4];
            float4 b0 = *(const float4*)&Bs[buf][kk][tx * 4];
            float4 b1 = *(const float4*)&Bs[buf][kk][64 + tx * 4];
            float ar[8] = {a0.x, a0.y, a0.z, a0.w, a1.x, a1.y, a1.z, a1.w};
            float br[8] = {b0.x, b0.y, b0.z, b0.w, b1.x, b1.y, b1.z, b1.w};
#pragma unroll
            for (int i = 0; i < 8; i++)
#pragma unroll
                for (int j = 0; j < 8; j++)
                    acc[i][j] += ar[i] * br[j];
        }

        if (more) {
            int nb = buf ^ 1;
            As[nb][lcol + 0][lrow] = a2.x;
            As[nb][lcol + 1][lrow] = a2.y;
            As[nb][lcol + 2][lrow] = a2.z;
            As[nb][lcol + 3][lrow] = a2.w;
            Bs[nb][lcol + 0][lrow] = b2.x;
            Bs[nb][lcol + 1][lrow] = b2.y;
            Bs[nb][lcol + 2][lrow] = b2.z;
            Bs[nb][lcol + 3][lrow] = b2.w;
            __syncthreads();
            buf = nb;
        }
    }

#pragma unroll
    for (int i = 0; i < 8; i++) {
        int row = mBase + ty * 8 + i;
        float* Crow = C + (size_t)row * HDIM + nBase;
        float vals[8];
#pragma unroll
        for (int j = 0; j < 8; j++) {
            float v = acc[i][j];
            if (act) v = 1.f / (1.f + __expf(-v));
            vals[j] = v;
        }
        *(float4*)(Crow + tx * 4)      = make_float4(vals[0], vals[1], vals[2], vals[3]);
        *(float4*)(Crow + 64 + tx * 4) = make_float4(vals[4], vals[5], vals[6], vals[7]);
    }
}

// Single-GEMM wrapper (output projection)
__global__ __launch_bounds__(256) void gemm_kernel(const float* __restrict__ A,
                                                   const float* __restrict__ W,
                                                   float* __restrict__ C,
                                                   int act)
{
    gemm_body(A, W, C, act);
}

// Batched 3-GEMM wrapper: z selects (A,W,C); z==2 gets sigmoid epilogue.
__global__ __launch_bounds__(256) void gemm3_kernel(const float* __restrict__ A0,
                                                    const float* __restrict__ W0,
                                                    float* __restrict__ C0,
                                                    const float* __restrict__ A1,
                                                    const float* __restrict__ W1,
                                                    float* __restrict__ C1,
                                                    const float* __restrict__ A2,
                                                    const float* __restrict__ W2,
                                                    float* __restrict__ C2)
{
    int z = blockIdx.z;
    const float* A = (z == 0) ? A0 : (z == 1) ? A1 : A2;
    const float* W = (z == 0) ? W0 : (z == 1) ? W1 : W2;
    float*       C = (z == 0) ? C0 : (z == 1) ? C1 : C2;
    gemm_body(A, W, C, z == 2 ? 1 : 0);
}

// ---------------------------------------------------------------------------
// WKV scan.  One thread per (b, h) channel, sequential over T.
// Fuses a = r * wkv.
// ---------------------------------------------------------------------------
__global__ void wkv_kernel(const float* __restrict__ k,
                           const float* __restrict__ v,
                           const float* __restrict__ r,
                           const float* __restrict__ w_,
                           const float* __restrict__ u_,
                           float* __restrict__ outA)
{
    int c = blockIdx.x * blockDim.x + threadIdx.x;   // 0..8191
    int b = c >> 10;
    int h = c & (HDIM - 1);
    float w = w_[h];
    float u = u_[h];

    int idx = b * TDIM * HDIM + h;

    float aa = 0.f, bb = 0.f, pp = -1e38f;
#pragma unroll 4
    for (int t = 0; t < TDIM; t++) {
        float kt = k[idx];
        float vt = v[idx];
        float rt = r[idx];

        float ww = u + kt;
        float p  = fmaxf(pp, ww);
        float e1 = __expf(pp - p);
        float e2 = __expf(ww - p);
        float num = e1 * aa + e2 * vt;
        float den = e1 * bb + e2 + 1e-9f;
        float wkv = __fdividef(num, den);
        outA[idx] = rt * wkv;

        float ww2 = w + pp;
        float p2  = fmaxf(ww2, kt);
        float e1b = __expf(ww2 - p2);
        float e2b = __expf(kt - p2);
        aa = e1b * aa + e2b * vt;
        bb = e1b * bb + e2b;
        pp = p2;

        idx += HDIM;
    }
}

// ---------------------------------------------------------------------------
// Launch.  Input order (metadata): x, time_decay, time_first, time_mix_k,
// time_mix_v, time_mix_r, W_k, W_v, W_r, W_o.  Output: float32 [B,T,H].
// ---------------------------------------------------------------------------
extern "C" void kernel_launch(void* const* d_in, const int* in_sizes, int n_in,
                              void* d_out, int out_size)
{
    const float* x   = (const float*)d_in[0];
    const float* td  = (const float*)d_in[1];
    const float* tf  = (const float*)d_in[2];
    const float* tmk = (const float*)d_in[3];
    const float* tmv = (const float*)d_in[4];
    const float* tmr = (const float*)d_in[5];
    const float* Wk  = (const float*)d_in[6];
    const float* Wv  = (const float*)d_in[7];
    const float* Wr  = (const float*)d_in[8];
    const float* Wo  = (const float*)d_in[9];
    float* out = (float*)d_out;

    void *pxk, *pxv, *pxr, *pk, *pv, *pr, *pa;
    cudaGetSymbolAddress(&pxk, g_xk);
    cudaGetSymbolAddress(&pxv, g_xv);
    cudaGetSymbolAddress(&pxr, g_xr);
    cudaGetSymbolAddress(&pk,  g_k);
    cudaGetSymbolAddress(&pv,  g_v);
    cudaGetSymbolAddress(&pr,  g_r);
    cudaGetSymbolAddress(&pa,  g_a);

    // 1) token-shift mix
    mix_kernel<<<MH / 4 / 256, 256>>>((const float4*)x,
                                      (const float4*)tmk,
                                      (const float4*)tmv,
                                      (const float4*)tmr,
                                      (float4*)pxk, (float4*)pxv, (float4*)pxr);

    // 2) three input GEMMs in one launch (sigmoid fused into r via z==2)
    dim3 g3(HDIM / 128, MDIM / 128, 3);   // (8, 128, 3)
    gemm3_kernel<<<g3, 256>>>((const float*)pxk, Wk, (float*)pk,
                              (const float*)pxv, Wv, (float*)pv,
                              (const float*)pxr, Wr, (float*)pr);

    // 3) WKV scan + fuse r*wkv
    wkv_kernel<<<BDIM * HDIM / 256, 256>>>((const float*)pk, (const float*)pv,
                                           (const float*)pr, td, tf, (float*)pa);

    // 4) output GEMM
    dim3 gg(HDIM / 128, MDIM / 128);
    gemm_kernel<<<gg, 256>>>((const float*)pa, Wo, out, 0);
}

// round 15
// speedup vs baseline: 2.2037x; 1.9439x over previous
#include <cuda_runtime.h>
#include <cuda_bf16.h>
#include <math.h>
#include <stdint.h>

// ---------------------------------------------------------------------------
// Problem constants
// ---------------------------------------------------------------------------
#define BDIM 8
#define TDIM 2048
#define HDIM 1024
#define MDIM (BDIM * TDIM)        // 16384 rows
#define MH   (MDIM * HDIM)        // 16,777,216 elements

// GEMM tiling (mma.sync path — sm_80-safe instructions only)
#define BM 128
#define BN 128
#define BK 32
#define NKT (HDIM / BK)           // 32 K-tiles
#define OFF_AH 0
#define OFF_AL 8192
#define OFF_BH 16384
#define OFF_BL 24576
#define STAGE_BYTES 32768
#define DSMEM_TOTAL (2 * STAGE_BYTES)   // 65536 bytes

// ---------------------------------------------------------------------------
// Scratch (allocation-free rule: __device__ globals)
// ---------------------------------------------------------------------------
__device__ __align__(256) __nv_bfloat16 g_xk_hi[MH];
__device__ __align__(256) __nv_bfloat16 g_xk_lo[MH];
__device__ __align__(256) __nv_bfloat16 g_xv_hi[MH];
__device__ __align__(256) __nv_bfloat16 g_xv_lo[MH];
__device__ __align__(256) __nv_bfloat16 g_xr_hi[MH];
__device__ __align__(256) __nv_bfloat16 g_xr_lo[MH];
__device__ __align__(256) __nv_bfloat16 g_w_hi[4 * HDIM * HDIM];  // k,v,r,o
__device__ __align__(256) __nv_bfloat16 g_w_lo[4 * HDIM * HDIM];
__device__ __align__(256) float g_k[MH];
__device__ __align__(256) float g_v[MH];
__device__ __align__(256) float g_r[MH];
__device__ __align__(256) __nv_bfloat16 g_a_hi[MH];
__device__ __align__(256) __nv_bfloat16 g_a_lo[MH];

// ---------------------------------------------------------------------------
// Helpers (all sm_80-level; NO tcgen05 / sm_103a-only features)
// ---------------------------------------------------------------------------
__device__ __forceinline__ uint32_t smem_u32(const void* p) {
    uint32_t a;
    asm("{ .reg .u64 t; cvta.to.shared.u64 t, %1; cvt.u32.u64 %0, t; }" : "=r"(a) : "l"(p));
    return a;
}

#define CP_ASYNC16(dst, src) \
    asm volatile("cp.async.cg.shared.global [%0], [%1], 16;\n" :: "r"(dst), "l"(src))
#define CP_COMMIT()  asm volatile("cp.async.commit_group;\n" ::: "memory")
#define CP_WAIT1()   asm volatile("cp.async.wait_group 1;\n" ::: "memory")

__device__ __forceinline__ void ldsm_x4(uint32_t* r, uint32_t addr) {
    asm volatile("ldmatrix.sync.aligned.m8n8.x4.shared.b16 {%0,%1,%2,%3}, [%4];"
        : "=r"(r[0]), "=r"(r[1]), "=r"(r[2]), "=r"(r[3]) : "r"(addr));
}

__device__ __forceinline__ void mma_bf16(float* d, const uint32_t* a, const uint32_t* b) {
    asm volatile(
        "mma.sync.aligned.m16n8k16.row.col.f32.bf16.bf16.f32 "
        "{%0,%1,%2,%3},{%4,%5,%6,%7},{%8,%9},{%0,%1,%2,%3};"
        : "+f"(d[0]), "+f"(d[1]), "+f"(d[2]), "+f"(d[3])
        : "r"(a[0]), "r"(a[1]), "r"(a[2]), "r"(a[3]), "r"(b[0]), "r"(b[1]));
}

// ---------------------------------------------------------------------------
// Kernel: split W matrices into bf16 hi/lo
// ---------------------------------------------------------------------------
__global__ void split_w_kernel(const float* __restrict__ Wk, const float* __restrict__ Wv,
                               const float* __restrict__ Wr, const float* __restrict__ Wo,
                               __nv_bfloat16* __restrict__ whi, __nv_bfloat16* __restrict__ wlo)
{
    int z = blockIdx.y;
    const float* src = (z == 0) ? Wk : (z == 1) ? Wv : (z == 2) ? Wr : Wo;
    int i = blockIdx.x * 256 + threadIdx.x;
    float w = src[i];
    __nv_bfloat16 h = __float2bfloat16(w);
    __nv_bfloat16 l = __float2bfloat16(w - __bfloat162float(h));
    whi[z * HDIM * HDIM + i] = h;
    wlo[z * HDIM * HDIM + i] = l;
}

// ---------------------------------------------------------------------------
// Kernel: token-shift mix -> bf16 hi/lo outputs
// ---------------------------------------------------------------------------
__global__ void mix_kernel(const float4* __restrict__ x,
                           const float4* __restrict__ mk4,
                           const float4* __restrict__ mv4,
                           const float4* __restrict__ mr4,
                           __nv_bfloat162* __restrict__ xkh, __nv_bfloat162* __restrict__ xkl,
                           __nv_bfloat162* __restrict__ xvh, __nv_bfloat162* __restrict__ xvl,
                           __nv_bfloat162* __restrict__ xrh, __nv_bfloat162* __restrict__ xrl)
{
    const int H4 = HDIM / 4;
    int i = blockIdx.x * blockDim.x + threadIdx.x;
    int h4 = i % H4;
    int m  = i / H4;
    int t  = m & (TDIM - 1);

    float4 xc = x[i];
    float4 xp = make_float4(0.f, 0.f, 0.f, 0.f);
    if (t != 0) xp = x[i - H4];

    float4 mk = mk4[h4], mv = mv4[h4], mr = mr4[h4];

    float ok[4], ov[4], orr[4];
    ok[0] = xc.x * mk.x + xp.x * (1.f - mk.x);
    ok[1] = xc.y * mk.y + xp.y * (1.f - mk.y);
    ok[2] = xc.z * mk.z + xp.z * (1.f - mk.z);
    ok[3] = xc.w * mk.w + xp.w * (1.f - mk.w);
    ov[0] = xc.x * mv.x + xp.x * (1.f - mv.x);
    ov[1] = xc.y * mv.y + xp.y * (1.f - mv.y);
    ov[2] = xc.z * mv.z + xp.z * (1.f - mv.z);
    ov[3] = xc.w * mv.w + xp.w * (1.f - mv.w);
    orr[0] = xc.x * mr.x + xp.x * (1.f - mr.x);
    orr[1] = xc.y * mr.y + xp.y * (1.f - mr.y);
    orr[2] = xc.z * mr.z + xp.z * (1.f - mr.z);
    orr[3] = xc.w * mr.w + xp.w * (1.f - mr.w);

#define SPLIT_STORE(vals, ph, pl)                                                  \
    {                                                                              \
        __nv_bfloat16 h0 = __float2bfloat16(vals[0]);                              \
        __nv_bfloat16 h1 = __float2bfloat16(vals[1]);                              \
        __nv_bfloat16 h2 = __float2bfloat16(vals[2]);                              \
        __nv_bfloat16 h3 = __float2bfloat16(vals[3]);                              \
        (ph)[i * 2]     = __nv_bfloat162(h0, h1);                                  \
        (ph)[i * 2 + 1] = __nv_bfloat162(h2, h3);                                  \
        (pl)[i * 2]     = __nv_bfloat162(                                          \
            __float2bfloat16(vals[0] - __bfloat162float(h0)),                      \
            __float2bfloat16(vals[1] - __bfloat162float(h1)));                     \
        (pl)[i * 2 + 1] = __nv_bfloat162(                                          \
            __float2bfloat16(vals[2] - __bfloat162float(h2)),                      \
            __float2bfloat16(vals[3] - __bfloat162float(h3)));                     \
    }
    SPLIT_STORE(ok, xkh, xkl);
    SPLIT_STORE(ov, xvh, xvl);
    SPLIT_STORE(orr, xrh, xrl);
#undef SPLIT_STORE
}

// ---------------------------------------------------------------------------
// Split-bf16 3-pass GEMM on mma.sync:  C[m,o] = sum_h A[m,h] * W[o,h]
// 128x128 tile, BK=32, 8 warps (4m x 2n -> 32x64 warp tile), cp.async 2-stage.
// Swizzle: 16B chunk c at (row,c) stored at c ^ ((row>>1)&3) -> conflict-free
// for both cp.async stores and ldmatrix 8x8 phases.
// ---------------------------------------------------------------------------
__device__ __forceinline__ void load_stage(uint32_t stg,
    const __nv_bfloat16* __restrict__ Ahi, const __nv_bfloat16* __restrict__ Alo,
    const __nv_bfloat16* __restrict__ Whi, const __nv_bfloat16* __restrict__ Wlo,
    int mBase, int nBase, int kBase, int tid)
{
#pragma unroll
    for (int j = 0; j < 2; ++j) {
        int idx = j * 256 + tid;           // 0..511
        int row = idx >> 2;                // 0..127
        int ch  = idx & 3;                 // 16B chunk within 64B row
        uint32_t sw = (uint32_t)(row * 64 + ((ch ^ ((row >> 1) & 3)) << 4));
        size_t gA = ((size_t)(mBase + row) * HDIM + kBase) * 2 + ch * 16;
        size_t gB = ((size_t)(nBase + row) * HDIM + kBase) * 2 + ch * 16;
        CP_ASYNC16(stg + OFF_AH + sw, (const char*)Ahi + gA);
        CP_ASYNC16(stg + OFF_AL + sw, (const char*)Alo + gA);
        CP_ASYNC16(stg + OFF_BH + sw, (const char*)Whi + gB);
        CP_ASYNC16(stg + OFF_BL + sw, (const char*)Wlo + gB);
    }
}

__device__ __forceinline__ void tgemm_body(
    const __nv_bfloat16* __restrict__ Ahi, const __nv_bfloat16* __restrict__ Alo,
    const __nv_bfloat16* __restrict__ Whi, const __nv_bfloat16* __restrict__ Wlo,
    float* __restrict__ C, int act)
{
    extern __shared__ char dsm[];
    uint32_t sb = smem_u32(dsm);
    int tid = threadIdx.x;
    int lane = tid & 31;
    int warp = tid >> 5;
    int wm = warp & 3;          // 0..3 -> m offset wm*32
    int wn = warp >> 2;         // 0..1 -> n offset wn*64
    int mBase = blockIdx.y * BM;
    int nBase = blockIdx.x * BN;

    // Lane-fixed ldmatrix address components
    int aRowSub = ((lane >> 3) & 1) * 8 + (lane & 7);  // A: m within 16
    int aKsub   = (lane >> 4) & 1;                     // A: k8-chunk
    int bRowSub = ((lane >> 4) & 1) * 8 + (lane & 7);  // B: n within 16
    int bKsub   = (lane >> 3) & 1;                     // B: k8-chunk

    float acc[2][8][4];
#pragma unroll
    for (int i = 0; i < 2; i++)
#pragma unroll
        for (int j = 0; j < 8; j++)
#pragma unroll
            for (int q = 0; q < 4; q++) acc[i][j][q] = 0.f;

    // Prologue: stages 0 and 1 in flight
    load_stage(sb, Ahi, Alo, Whi, Wlo, mBase, nBase, 0, tid);
    CP_COMMIT();
    load_stage(sb + STAGE_BYTES, Ahi, Alo, Whi, Wlo, mBase, nBase, BK, tid);
    CP_COMMIT();

    for (int it = 0; it < NKT; ++it) {
        uint32_t stg = sb + (it & 1) * STAGE_BYTES;
        CP_WAIT1();
        __syncthreads();

#pragma unroll
        for (int ks = 0; ks < 2; ++ks) {
            uint32_t ah[2][4], al[2][4], bh[4][4], bl[4][4];
            // A fragments (hi & lo): mf in {0,1} covers warp's 32 m-rows
#pragma unroll
            for (int mf = 0; mf < 2; ++mf) {
                int row = wm * 32 + mf * 16 + aRowSub;
                int ch  = ks * 2 + aKsub;
                uint32_t off = (uint32_t)(row * 64 + ((ch ^ ((row >> 1) & 3)) << 4));
                ldsm_x4(ah[mf], stg + OFF_AH + off);
                ldsm_x4(al[mf], stg + OFF_AL + off);
            }
            // B fragments (hi & lo): nb in 0..3, each x4 covers 16 n
#pragma unroll
            for (int nb = 0; nb < 4; ++nb) {
                int row = wn * 64 + nb * 16 + bRowSub;
                int ch  = ks * 2 + bKsub;
                uint32_t off = (uint32_t)(row * 64 + ((ch ^ ((row >> 1) & 3)) << 4));
                ldsm_x4(bh[nb], stg + OFF_BH + off);
                ldsm_x4(bl[nb], stg + OFF_BL + off);
            }
            // 3 passes: ah*bh + ah*bl + al*bh
#pragma unroll
            for (int mf = 0; mf < 2; ++mf)
#pragma unroll
                for (int nb = 0; nb < 4; ++nb) {
                    mma_bf16(acc[mf][nb * 2 + 0], ah[mf], &bh[nb][0]);
                    mma_bf16(acc[mf][nb * 2 + 1], ah[mf], &bh[nb][2]);
                    mma_bf16(acc[mf][nb * 2 + 0], ah[mf], &bl[nb][0]);
                    mma_bf16(acc[mf][nb * 2 + 1], ah[mf], &bl[nb][2]);
                    mma_bf16(acc[mf][nb * 2 + 0], al[mf], &bh[nb][0]);
                    mma_bf16(acc[mf][nb * 2 + 1], al[mf], &bh[nb][2]);
                }
        }

        __syncthreads();
        if (it + 2 < NKT)
            load_stage(stg, Ahi, Alo, Whi, Wlo, mBase, nBase, (it + 2) * BK, tid);
        CP_COMMIT();
    }

    // Epilogue: acc tile (mf,nf): rows m,m+8 = lane>>2 (+8); cols 2*(lane&3)+{0,1}
#pragma unroll
    for (int mf = 0; mf < 2; ++mf) {
        int m0 = mBase + wm * 32 + mf * 16 + (lane >> 2);
#pragma unroll
        for (int nf = 0; nf < 8; ++nf) {
            int nc = nBase + wn * 64 + nf * 8 + (lane & 3) * 2;
            float v0 = acc[mf][nf][0], v1 = acc[mf][nf][1];
            float v2 = acc[mf][nf][2], v3 = acc[mf][nf][3];
            if (act) {
                v0 = 1.f / (1.f + __expf(-v0));
                v1 = 1.f / (1.f + __expf(-v1));
                v2 = 1.f / (1.f + __expf(-v2));
                v3 = 1.f / (1.f + __expf(-v3));
            }
            *(float2*)(C + (size_t)m0 * HDIM + nc)       = make_float2(v0, v1);
            *(float2*)(C + (size_t)(m0 + 8) * HDIM + nc) = make_float2(v2, v3);
        }
    }
}

__global__ __launch_bounds__(256, 1)
void tgemm_kernel(const __nv_bfloat16* Ahi, const __nv_bfloat16* Alo,
                  const __nv_bfloat16* Whi, const __nv_bfloat16* Wlo,
                  float* C, int act)
{
    tgemm_body(Ahi, Alo, Whi, Wlo, C, act);
}

__global__ __launch_bounds__(256, 1)
void tgemm3_kernel(const __nv_bfloat16* A0h, const __nv_bfloat16* A0l,
                   const __nv_bfloat16* A1h, const __nv_bfloat16* A1l,
                   const __nv_bfloat16* A2h, const __nv_bfloat16* A2l,
                   const __nv_bfloat16* Wh,  const __nv_bfloat16* Wl,
                   float* C0, float* C1, float* C2)
{
    int z = blockIdx.z;
    const __nv_bfloat16* Ah = (z == 0) ? A0h : (z == 1) ? A1h : A2h;
    const __nv_bfloat16* Al = (z == 0) ? A0l : (z == 1) ? A1l : A2l;
    float* C = (z == 0) ? C0 : (z == 1) ? C1 : C2;
    tgemm_body(Ah, Al, Wh + (size_t)z * HDIM * HDIM, Wl + (size_t)z * HDIM * HDIM, C, z == 2);
}

// ---------------------------------------------------------------------------
// WKV scan: one thread per (b,h), fuses a = r*wkv -> bf16 hi/lo
// ---------------------------------------------------------------------------
__global__ void wkv_kernel(const float* __restrict__ k,
                           const float* __restrict__ v,
                           const float* __restrict__ r,
                           const float* __restrict__ w_,
                           const float* __restrict__ u_,
                           __nv_bfloat16* __restrict__ ah,
                           __nv_bfloat16* __restrict__ al)
{
    int c = blockIdx.x * blockDim.x + threadIdx.x;
    int b = c >> 10;
    int h = c & (HDIM - 1);
    float w = w_[h];
    float u = u_[h];
    int idx = b * TDIM * HDIM + h;

    float aa = 0.f, bb = 0.f, pp = -1e38f;
#pragma unroll 4
    for (int t = 0; t < TDIM; t++) {
        float kt = k[idx];
        float vt = v[idx];
        float rt = r[idx];

        float ww = u + kt;
        float p  = fmaxf(pp, ww);
        float e1 = __expf(pp - p);
        float e2 = __expf(ww - p);
        float num = e1 * aa + e2 * vt;
        float den = e1 * bb + e2 + 1e-9f;
        float aval = rt * __fdividef(num, den);

        __nv_bfloat16 hi = __float2bfloat16(aval);
        ah[idx] = hi;
        al[idx] = __float2bfloat16(aval - __bfloat162float(hi));

        float ww2 = w + pp;
        float p2  = fmaxf(ww2, kt);
        float e1b = __expf(ww2 - p2);
        float e2b = __expf(kt - p2);
        aa = e1b * aa + e2b * vt;
        bb = e1b * bb + e2b;
        pp = p2;

        idx += HDIM;
    }
}

// ---------------------------------------------------------------------------
// Launch. Inputs: x, time_decay, time_first, time_mix_k/v/r, W_k, W_v, W_r, W_o
// ---------------------------------------------------------------------------
extern "C" void kernel_launch(void* const* d_in, const int* in_sizes, int n_in,
                              void* d_out, int out_size)
{
    const float* x   = (const float*)d_in[0];
    const float* td  = (const float*)d_in[1];
    const float* tf  = (const float*)d_in[2];
    const float* tmk = (const float*)d_in[3];
    const float* tmv = (const float*)d_in[4];
    const float* tmr = (const float*)d_in[5];
    const float* Wk  = (const float*)d_in[6];
    const float* Wv  = (const float*)d_in[7];
    const float* Wr  = (const float*)d_in[8];
    const float* Wo  = (const float*)d_in[9];
    float* out = (float*)d_out;

    void *pxkh, *pxkl, *pxvh, *pxvl, *pxrh, *pxrl, *pwh, *pwl, *pk, *pv, *pr, *pah, *pal;
    cudaGetSymbolAddress(&pxkh, g_xk_hi);
    cudaGetSymbolAddress(&pxkl, g_xk_lo);
    cudaGetSymbolAddress(&pxvh, g_xv_hi);
    cudaGetSymbolAddress(&pxvl, g_xv_lo);
    cudaGetSymbolAddress(&pxrh, g_xr_hi);
    cudaGetSymbolAddress(&pxrl, g_xr_lo);
    cudaGetSymbolAddress(&pwh,  g_w_hi);
    cudaGetSymbolAddress(&pwl,  g_w_lo);
    cudaGetSymbolAddress(&pk,   g_k);
    cudaGetSymbolAddress(&pv,   g_v);
    cudaGetSymbolAddress(&pr,   g_r);
    cudaGetSymbolAddress(&pah,  g_a_hi);
    cudaGetSymbolAddress(&pal,  g_a_lo);

    cudaFuncSetAttribute(tgemm_kernel,  cudaFuncAttributeMaxDynamicSharedMemorySize, DSMEM_TOTAL);
    cudaFuncSetAttribute(tgemm3_kernel, cudaFuncAttributeMaxDynamicSharedMemorySize, DSMEM_TOTAL);

    // 1) split weights to bf16 hi/lo
    split_w_kernel<<<dim3(HDIM * HDIM / 256, 4), 256>>>(
        Wk, Wv, Wr, Wo, (__nv_bfloat16*)pwh, (__nv_bfloat16*)pwl);

    // 2) token-shift mix -> bf16 hi/lo activations
    mix_kernel<<<MH / 4 / 256, 256>>>(
        (const float4*)x, (const float4*)tmk, (const float4*)tmv, (const float4*)tmr,
        (__nv_bfloat162*)pxkh, (__nv_bfloat162*)pxkl,
        (__nv_bfloat162*)pxvh, (__nv_bfloat162*)pxvl,
        (__nv_bfloat162*)pxrh, (__nv_bfloat162*)pxrl);

    // 3) three input GEMMs on tensor cores (sigmoid fused for z==2)
    tgemm3_kernel<<<dim3(HDIM / BN, MDIM / BM, 3), 256, DSMEM_TOTAL>>>(
        (const __nv_bfloat16*)pxkh, (const __nv_bfloat16*)pxkl,
        (const __nv_bfloat16*)pxvh, (const __nv_bfloat16*)pxvl,
        (const __nv_bfloat16*)pxrh, (const __nv_bfloat16*)pxrl,
        (const __nv_bfloat16*)pwh,  (const __nv_bfloat16*)pwl,
        (float*)pk, (float*)pv, (float*)pr);

    // 4) WKV scan -> a = r*wkv as bf16 hi/lo
    wkv_kernel<<<BDIM * HDIM / 256, 256>>>(
        (const float*)pk, (const float*)pv, (const float*)pr, td, tf,
        (__nv_bfloat16*)pah, (__nv_bfloat16*)pal);

    // 5) output GEMM
    tgemm_kernel<<<dim3(HDIM / BN, MDIM / BM), 256, DSMEM_TOTAL>>>(
        (const __nv_bfloat16*)pah, (const __nv_bfloat16*)pal,
        (const __nv_bfloat16*)pwh + (size_t)3 * HDIM * HDIM,
        (const __nv_bfloat16*)pwl + (size_t)3 * HDIM * HDIM,
        out, 0);
}